// round 7
// baseline (speedup 1.0000x reference)
#include <cuda_runtime.h>
#include <math.h>

#define NH  12
#define HD  64
#define DIM 768
#define NB  8
#define SL  1024

// Scratch (allocation-free rule: __device__ globals)
__device__ float g_Q[(size_t)NB*NH*SL*HD];
__device__ float g_K[(size_t)NB*NH*SL*HD];   // stored pre-rounded to tf32 grid
__device__ float g_V[(size_t)NB*NH*SL*HD];   // stored pre-rounded to tf32 grid
__device__ float g_O[(size_t)NB*SL*DIM];
__device__ float g_Ar[(size_t)8192*DIM];     // hidden, RNA-rounded to tf32
__device__ float g_Wr[(size_t)2304*DIM];     // W, RNA-rounded to tf32

// ---------------------------------------------------------------------------
// helpers
// ---------------------------------------------------------------------------
__device__ __forceinline__ unsigned f2tf(float f) {
    unsigned u; asm("cvt.rna.tf32.f32 %0, %1;" : "=r"(u) : "f"(f)); return u;
}
__device__ __forceinline__ void mma_tf32(float* c, const unsigned* a, const unsigned* b) {
    asm volatile("mma.sync.aligned.m16n8k8.row.col.f32.tf32.tf32.f32 "
                 "{%0,%1,%2,%3}, {%4,%5,%6,%7}, {%8,%9}, {%0,%1,%2,%3};"
                 : "+f"(c[0]), "+f"(c[1]), "+f"(c[2]), "+f"(c[3])
                 : "r"(a[0]), "r"(a[1]), "r"(a[2]), "r"(a[3]),
                   "r"(b[0]), "r"(b[1]));
}
__device__ __forceinline__ void cpa16(unsigned sdst, const void* gsrc) {
    asm volatile("cp.async.cg.shared.global [%0], [%1], 16;" :: "r"(sdst), "l"(gsrc));
}
__device__ __forceinline__ void cpa_commit() { asm volatile("cp.async.commit_group;"); }
template<int N> __device__ __forceinline__ void cpa_wait() {
    asm volatile("cp.async.wait_group %0;" :: "n"(N));
}

// ---------------------------------------------------------------------------
// Prep (fused): zero K/V pads; RNA-round GEMM inputs to the tf32 grid.
// ---------------------------------------------------------------------------
__global__ void prep_kernel(const float* __restrict__ A, const float* __restrict__ W) {
    const int nZ = NB*NH*SL*HD/4;        // float4 count for K (and V)
    const int nA = 8192*DIM/4;
    const int nW = 2304*DIM/4;
    const int total = nZ + nA + nW;
    for (int i = blockIdx.x * blockDim.x + threadIdx.x; i < total;
         i += gridDim.x * blockDim.x) {
        if (i < nZ) {
            ((float4*)g_K)[i] = make_float4(0.f,0.f,0.f,0.f);
            ((float4*)g_V)[i] = make_float4(0.f,0.f,0.f,0.f);
        } else if (i < nZ + nA) {
            float4 v = ((const float4*)A)[i - nZ];
            ((uint4*)g_Ar)[i - nZ] = make_uint4(f2tf(v.x), f2tf(v.y), f2tf(v.z), f2tf(v.w));
        } else {
            float4 v = ((const float4*)W)[i - nZ - nA];
            ((uint4*)g_Wr)[i - nZ - nA] = make_uint4(f2tf(v.x), f2tf(v.y), f2tf(v.z), f2tf(v.w));
        }
    }
}

// ---------------------------------------------------------------------------
// QKV GEMM (tf32 mma, 2-stage cp.async): C[8192,2304] = A @ W^T + b, scatter.
// Block tile 128x128, K panel 32, 8 warps 2(M)x4(N), warp tile 64x32.
// ---------------------------------------------------------------------------
#define GP 36
#define G_NT (DIM/32)
#define G_SMEM_BYTES (2*(128+128)*GP*4)
__global__ __launch_bounds__(256, 2) void qkv_gemm_kernel(
    const float* __restrict__ wb,
    const int*   __restrict__ indices)
{
    extern __shared__ unsigned gsm[];
    unsigned* Asm = gsm;                 // 2 x 128 x GP
    unsigned* Bsm = gsm + 2*128*GP;      // 2 x 128 x GP

    const int tid  = threadIdx.x;
    const int lane = tid & 31;
    const int wid  = tid >> 5;
    const int lr = lane >> 2, lm = lane & 3;
    const int wm = (wid & 1) * 64;       // warp M offset
    const int wn = (wid >> 1) * 32;      // warp N offset
    const int i0 = blockIdx.y * 128;
    const int j0 = blockIdx.x * 128;
    const unsigned smem_base = (unsigned)__cvta_generic_to_shared(gsm);

    float acc[4][4][4];
    #pragma unroll
    for (int mt = 0; mt < 4; mt++)
        #pragma unroll
        for (int nt = 0; nt < 4; nt++)
            #pragma unroll
            for (int r = 0; r < 4; r++) acc[mt][nt][r] = 0.f;

    auto issue = [&](int kt, int buf) {
        const int k0 = kt * 32;
        #pragma unroll
        for (int t = 0; t < 4; t++) {               // A: 128x32
            int c = tid + t*256;
            int r = c >> 3, kc = c & 7;
            cpa16(smem_base + (buf*128*GP + r*GP + kc*4)*4,
                  &g_Ar[(size_t)(i0 + r)*DIM + k0 + kc*4]);
        }
        #pragma unroll
        for (int t = 0; t < 4; t++) {               // B: 128x32
            int c = tid + t*256;
            int r = c >> 3, kc = c & 7;
            cpa16(smem_base + (2*128*GP + buf*128*GP + r*GP + kc*4)*4,
                  &g_Wr[(size_t)(j0 + r)*DIM + k0 + kc*4]);
        }
        cpa_commit();
    };

    issue(0, 0);
    for (int kt = 0; kt < G_NT; kt++) {
        const int buf = kt & 1;
        if (kt + 1 < G_NT) { issue(kt + 1, buf ^ 1); cpa_wait<1>(); }
        else               { cpa_wait<0>(); }
        __syncthreads();

        const unsigned* As = Asm + buf*128*GP;
        const unsigned* Bs = Bsm + buf*128*GP;
        #pragma unroll
        for (int kc = 0; kc < 4; kc++) {
            unsigned a[4][4], b[4][2];
            #pragma unroll
            for (int mt = 0; mt < 4; mt++) {
                a[mt][0] = As[(wm + mt*16 + lr    )*GP + kc*8 + lm    ];
                a[mt][1] = As[(wm + mt*16 + lr + 8)*GP + kc*8 + lm    ];
                a[mt][2] = As[(wm + mt*16 + lr    )*GP + kc*8 + lm + 4];
                a[mt][3] = As[(wm + mt*16 + lr + 8)*GP + kc*8 + lm + 4];
            }
            #pragma unroll
            for (int nt = 0; nt < 4; nt++) {
                b[nt][0] = Bs[(wn + nt*8 + lr)*GP + kc*8 + lm    ];
                b[nt][1] = Bs[(wn + nt*8 + lr)*GP + kc*8 + lm + 4];
            }
            #pragma unroll
            for (int mt = 0; mt < 4; mt++)
                #pragma unroll
                for (int nt = 0; nt < 4; nt++)
                    mma_tf32(acc[mt][nt], a[mt], b[nt]);
        }
        __syncthreads();
    }

    // Epilogue: 128-col tile never crosses the Q/K/V boundary (768 = 6*128)
    // but spans two heads; resolve head per column.
    const int t = j0 / DIM;
    const int jbase = j0 % DIM;
    float* dst = (t == 0) ? g_Q : (t == 1) ? g_K : g_V;
    const bool do_round = (t != 0);

    #pragma unroll
    for (int mt = 0; mt < 4; mt++) {
        #pragma unroll
        for (int half = 0; half < 2; half++) {
            const int gi = i0 + wm + mt*16 + lr + half*8;
            const int pr = indices[gi];
            const int bb = pr / SL;
            const int ss = pr % SL;
            #pragma unroll
            for (int nt = 0; nt < 4; nt++) {
                const int col = wn + nt*8 + 2*lm;
                const int jc = jbase + col;
                const int hh = jc >> 6, dd = jc & 63;
                float2 bv = *(const float2*)&wb[j0 + col];
                float2 o;
                o.x = acc[mt][nt][half*2+0] + bv.x;
                o.y = acc[mt][nt][half*2+1] + bv.y;
                if (do_round) {
                    o.x = __uint_as_float(f2tf(o.x));
                    o.y = __uint_as_float(f2tf(o.y));
                }
                *(float2*)&dst[(((size_t)bb*NH + hh)*SL + ss)*HD + dd] = o;
            }
        }
    }
}

// ---------------------------------------------------------------------------
// Fused attention v5. CTA = 256 q-rows, 512 threads: 16 warps x 16 q-rows,
// each warp covers the full 64-kv tile. Same staging amortization as v4 but
// double the warps/SMSP (4 vs 2) at ~half the per-warp register state
// (qa/s/o = 96 regs) -> latency hiding doubles.
// Bias loads straight into the S accumulators (init C=bias); K/V double-
// buffered via cp.async; PV uses kv-permutation pi=[0,2,4,6,1,3,5,7] so the
// S-acc layout == A-fragment layout (no shuffles).
// ---------------------------------------------------------------------------
#define KPAD 68
#define VPAD 68
#define A_KOFF 0
#define A_VOFF (2*64*KPAD)
#define A_SMEM_WORDS (A_VOFF + 2*64*VPAD)
#define QROWS 256
#define ATHREADS 512
__global__ __launch_bounds__(ATHREADS, 1) void attn_kernel(const float* __restrict__ bias)
{
    extern __shared__ unsigned asm_[];
    const int tid  = threadIdx.x;
    const int lane = tid & 31;
    const int wid  = tid >> 5;           // 0..15
    const int lr = lane >> 2, lm = lane & 3;
    const int bh = blockIdx.y;
    const int b  = bh / NH, h = bh % NH;
    const int q0 = blockIdx.x * QROWS;
    const unsigned smem_base = (unsigned)__cvta_generic_to_shared(asm_);

    const float* qp = g_Q + (size_t)bh * SL * HD;
    const float* kp = g_K + (size_t)bh * SL * HD;
    const float* vp = g_V + (size_t)bh * SL * HD;
    // this warp's bias panel: rows q0 + wid*16 ..
    const float* bW = bias + ((size_t)bh * SL + q0 + wid*16) * SL;

    auto issue = [&](int kt, int buf) {
        const int kb = kt * 64;
        #pragma unroll
        for (int t = 0; t < 2; t++) {               // K: 64x64 = 1024 chunks
            int c = tid + t*ATHREADS;
            int kv = c >> 4, dc = c & 15;
            cpa16(smem_base + (A_KOFF + buf*64*KPAD + kv*KPAD + dc*4)*4,
                  &kp[(size_t)(kb + kv)*HD + dc*4]);
        }
        #pragma unroll
        for (int t = 0; t < 2; t++) {               // V: 64x64
            int c = tid + t*ATHREADS;
            int kv = c >> 4, dc = c & 15;
            cpa16(smem_base + (A_VOFF + buf*64*VPAD + kv*VPAD + dc*4)*4,
                  &vp[(size_t)(kb + kv)*HD + dc*4]);
        }
        cpa_commit();
    };

    issue(0, 0);

    // Q fragments (x 1/8) for this warp's 16 rows, loaded once from gmem.
    unsigned qa[8][4];
    {
        const int qrow = q0 + wid*16 + lr;
        #pragma unroll
        for (int kc = 0; kc < 8; kc++) {
            qa[kc][0] = f2tf(0.125f * qp[(size_t)(qrow    )*HD + kc*8 + lm    ]);
            qa[kc][1] = f2tf(0.125f * qp[(size_t)(qrow + 8)*HD + kc*8 + lm    ]);
            qa[kc][2] = f2tf(0.125f * qp[(size_t)(qrow    )*HD + kc*8 + lm + 4]);
            qa[kc][3] = f2tf(0.125f * qp[(size_t)(qrow + 8)*HD + kc*8 + lm + 4]);
        }
    }

    float o[8][4];
    #pragma unroll
    for (int dt = 0; dt < 8; dt++)
        #pragma unroll
        for (int r = 0; r < 4; r++) o[dt][r] = 0.f;
    float l0 = 0.f, l1 = 0.f;

    for (int kt = 0; kt < SL/64; kt++) {
        const int buf = kt & 1;
        if (kt + 1 < SL/64) issue(kt + 1, buf ^ 1);

        // S accumulators initialized with bias straight from gmem (consumed
        // only after the 64-mma QK chain -> DRAM latency hidden).
        float s[8][4];
        {
            const float* bp = bW + kt*64;
            #pragma unroll
            for (int nt = 0; nt < 8; nt++) {
                float2 t0 = *(const float2*)&bp[(size_t)(lr    )*SL + nt*8 + 2*lm];
                float2 t1 = *(const float2*)&bp[(size_t)(lr + 8)*SL + nt*8 + 2*lm];
                s[nt][0] = t0.x; s[nt][1] = t0.y;
                s[nt][2] = t1.x; s[nt][3] = t1.y;
            }
        }

        if (kt + 1 < SL/64) cpa_wait<1>(); else cpa_wait<0>();
        __syncthreads();

        const unsigned* Ks = asm_ + A_KOFF + buf*64*KPAD;
        const unsigned* Vs = asm_ + A_VOFF + buf*64*VPAD;

        // S += (Q/8) K^T over the full 64 kv
        #pragma unroll
        for (int kc = 0; kc < 8; kc++) {
            #pragma unroll
            for (int nt = 0; nt < 8; nt++) {
                unsigned bk[2];
                bk[0] = Ks[(nt*8 + lr)*KPAD + kc*8 + lm    ];
                bk[1] = Ks[(nt*8 + lr)*KPAD + kc*8 + lm + 4];
                mma_tf32(s[nt], qa[kc], bk);
            }
        }

        // P = exp(S); partial row sums
        #pragma unroll
        for (int nt = 0; nt < 8; nt++) {
            s[nt][0] = __expf(s[nt][0]);
            s[nt][1] = __expf(s[nt][1]);
            s[nt][2] = __expf(s[nt][2]);
            s[nt][3] = __expf(s[nt][3]);
            l0 += s[nt][0] + s[nt][1];
            l1 += s[nt][2] + s[nt][3];
        }

        // O += P V with kv permuted pi=[0,2,4,6,1,3,5,7] inside each 8-block:
        // acc layout == A-fragment layout, V B-frag reads rows cb+2lm, cb+2lm+1.
        #pragma unroll
        for (int kc = 0; kc < 8; kc++) {
            const int cb = kc*8;
            unsigned pa[4];
            pa[0] = f2tf(s[kc][0]); pa[1] = f2tf(s[kc][2]);
            pa[2] = f2tf(s[kc][1]); pa[3] = f2tf(s[kc][3]);
            #pragma unroll
            for (int dt = 0; dt < 8; dt++) {
                unsigned bv[2];
                bv[0] = Vs[(cb + 2*lm    )*VPAD + dt*8 + lr];
                bv[1] = Vs[(cb + 2*lm + 1)*VPAD + dt*8 + lr];
                mma_tf32(o[dt], pa, bv);
            }
        }
        __syncthreads();
    }

    // Normalize and store (each warp owns its rows fully; no merge).
    l0 += __shfl_xor_sync(0xffffffffu, l0, 1);
    l0 += __shfl_xor_sync(0xffffffffu, l0, 2);
    l1 += __shfl_xor_sync(0xffffffffu, l1, 1);
    l1 += __shfl_xor_sync(0xffffffffu, l1, 2);
    const float inv0 = 1.0f / l0;
    const float inv1 = 1.0f / l1;

    const int row0 = b*SL + q0 + wid*16 + lr;
    float* orow0 = &g_O[(size_t)row0 * DIM + h*HD];
    float* orow1 = orow0 + (size_t)8 * DIM;
    #pragma unroll
    for (int dt = 0; dt < 8; dt++) {
        *(float2*)&orow0[dt*8 + 2*lm] = make_float2(o[dt][0]*inv0, o[dt][1]*inv0);
        *(float2*)&orow1[dt*8 + 2*lm] = make_float2(o[dt][2]*inv1, o[dt][3]*inv1);
    }
}

// ---------------------------------------------------------------------------
// Gather: out[i,:] = O_padded[indices[i],:]
// ---------------------------------------------------------------------------
__global__ void gather_kernel(const int* __restrict__ indices,
                              float* __restrict__ out, int nnz)
{
    int e = blockIdx.x * blockDim.x + threadIdx.x;
    const int per_row = DIM / 4;
    int total = nnz * per_row;
    if (e < total) {
        int row = e / per_row;
        int c = (e % per_row) * 4;
        *(float4*)&out[(size_t)row*DIM + c] =
            *(const float4*)&g_O[(size_t)indices[row]*DIM + c];
    }
}

// ---------------------------------------------------------------------------
extern "C" void kernel_launch(void* const* d_in, const int* in_sizes, int n_in,
                              void* d_out, int out_size)
{
    const float* hidden  = (const float*)d_in[0];
    const int*   indices = (const int*)  d_in[3];
    const float* bias    = (const float*)d_in[5];
    const float* Wqkv_w  = (const float*)d_in[7];
    const float* Wqkv_b  = (const float*)d_in[8];
    const int nnz = in_sizes[0] / DIM;   // 8192

    static bool attr_done = false;
    if (!attr_done) {
        cudaFuncSetAttribute(qkv_gemm_kernel,
            cudaFuncAttributeMaxDynamicSharedMemorySize, G_SMEM_BYTES);
        cudaFuncSetAttribute(attn_kernel,
            cudaFuncAttributeMaxDynamicSharedMemorySize, A_SMEM_WORDS*4);
        attr_done = true;
    }

    prep_kernel<<<2048, 256>>>(hidden, Wqkv_w);
    qkv_gemm_kernel<<<dim3(3*DIM/128, nnz/128), 256, G_SMEM_BYTES>>>(Wqkv_b, indices);
    attn_kernel<<<dim3(SL/QROWS, NB*NH), ATHREADS, A_SMEM_WORDS*4>>>(bias);
    gather_kernel<<<(nnz*(DIM/4) + 255)/256, 256>>>(indices, (float*)d_out, nnz);
}

// round 9
// speedup vs baseline: 1.0141x; 1.0141x over previous
#include <cuda_runtime.h>
#include <math.h>

#define NH  12
#define HD  64
#define DIM 768
#define NB  8
#define SL  1024

// Scratch (allocation-free rule: __device__ globals)
__device__ float g_Q[(size_t)NB*NH*SL*HD];
__device__ float g_K[(size_t)NB*NH*SL*HD];   // stored pre-rounded to tf32 grid
__device__ float g_V[(size_t)NB*NH*SL*HD];   // stored pre-rounded to tf32 grid
__device__ float g_Ar[(size_t)8192*DIM];     // hidden, RNA-rounded to tf32
__device__ float g_Wr[(size_t)2304*DIM];     // W, RNA-rounded to tf32
__device__ int   g_inv[NB*SL];               // padded row -> output row (-1 = none)

// ---------------------------------------------------------------------------
// helpers
// ---------------------------------------------------------------------------
__device__ __forceinline__ unsigned f2tf(float f) {
    unsigned u; asm("cvt.rna.tf32.f32 %0, %1;" : "=r"(u) : "f"(f)); return u;
}
__device__ __forceinline__ void mma_tf32(float* c, const unsigned* a, const unsigned* b) {
    asm volatile("mma.sync.aligned.m16n8k8.row.col.f32.tf32.tf32.f32 "
                 "{%0,%1,%2,%3}, {%4,%5,%6,%7}, {%8,%9}, {%0,%1,%2,%3};"
                 : "+f"(c[0]), "+f"(c[1]), "+f"(c[2]), "+f"(c[3])
                 : "r"(a[0]), "r"(a[1]), "r"(a[2]), "r"(a[3]),
                   "r"(b[0]), "r"(b[1]));
}
__device__ __forceinline__ void cpa16(unsigned sdst, const void* gsrc) {
    asm volatile("cp.async.cg.shared.global [%0], [%1], 16;" :: "r"(sdst), "l"(gsrc));
}
__device__ __forceinline__ void cpa_commit() { asm volatile("cp.async.commit_group;"); }
template<int N> __device__ __forceinline__ void cpa_wait() {
    asm volatile("cp.async.wait_group %0;" :: "n"(N));
}

// ---------------------------------------------------------------------------
// Prep (fused): zero K/V pads; init g_inv = -1; RNA-round GEMM inputs.
// ---------------------------------------------------------------------------
__global__ void prep_kernel(const float* __restrict__ A, const float* __restrict__ W) {
    const int nZ = NB*NH*SL*HD/4;
    const int nI = NB*SL;
    const int nA = 8192*DIM/4;
    const int nW = 2304*DIM/4;
    const int total = nZ + nI + nA + nW;
    for (int i = blockIdx.x * blockDim.x + threadIdx.x; i < total;
         i += gridDim.x * blockDim.x) {
        if (i < nZ) {
            ((float4*)g_K)[i] = make_float4(0.f,0.f,0.f,0.f);
            ((float4*)g_V)[i] = make_float4(0.f,0.f,0.f,0.f);
        } else if (i < nZ + nI) {
            g_inv[i - nZ] = -1;
        } else if (i < nZ + nI + nA) {
            float4 v = ((const float4*)A)[i - nZ - nI];
            ((uint4*)g_Ar)[i - nZ - nI] = make_uint4(f2tf(v.x), f2tf(v.y), f2tf(v.z), f2tf(v.w));
        } else {
            float4 v = ((const float4*)W)[i - nZ - nI - nA];
            ((uint4*)g_Wr)[i - nZ - nI - nA] = make_uint4(f2tf(v.x), f2tf(v.y), f2tf(v.z), f2tf(v.w));
        }
    }
}

// ---------------------------------------------------------------------------
// QKV GEMM (tf32 mma, 2-stage cp.async): C[8192,2304] = A @ W^T + b, scatter.
// Block tile 128x128, K panel 32, 8 warps 2(M)x4(N), warp tile 64x32.
// j0==0 blocks also publish g_inv (padded row -> out row).
// ---------------------------------------------------------------------------
#define GP 36
#define G_NT (DIM/32)
#define G_SMEM_BYTES (2*(128+128)*GP*4)
__global__ __launch_bounds__(256, 2) void qkv_gemm_kernel(
    const float* __restrict__ wb,
    const int*   __restrict__ indices)
{
    extern __shared__ unsigned gsm[];
    unsigned* Asm = gsm;                 // 2 x 128 x GP
    unsigned* Bsm = gsm + 2*128*GP;      // 2 x 128 x GP

    const int tid  = threadIdx.x;
    const int lane = tid & 31;
    const int wid  = tid >> 5;
    const int lr = lane >> 2, lm = lane & 3;
    const int wm = (wid & 1) * 64;       // warp M offset
    const int wn = (wid >> 1) * 32;      // warp N offset
    const int i0 = blockIdx.y * 128;
    const int j0 = blockIdx.x * 128;
    const unsigned smem_base = (unsigned)__cvta_generic_to_shared(gsm);

    // publish inverse mapping once (j-block 0 only)
    if (blockIdx.x == 0 && tid < 128) {
        const int gi = i0 + tid;
        g_inv[indices[gi]] = gi;
    }

    float acc[4][4][4];
    #pragma unroll
    for (int mt = 0; mt < 4; mt++)
        #pragma unroll
        for (int nt = 0; nt < 4; nt++)
            #pragma unroll
            for (int r = 0; r < 4; r++) acc[mt][nt][r] = 0.f;

    auto issue = [&](int kt, int buf) {
        const int k0 = kt * 32;
        #pragma unroll
        for (int t = 0; t < 4; t++) {               // A: 128x32
            int c = tid + t*256;
            int r = c >> 3, kc = c & 7;
            cpa16(smem_base + (buf*128*GP + r*GP + kc*4)*4,
                  &g_Ar[(size_t)(i0 + r)*DIM + k0 + kc*4]);
        }
        #pragma unroll
        for (int t = 0; t < 4; t++) {               // B: 128x32
            int c = tid + t*256;
            int r = c >> 3, kc = c & 7;
            cpa16(smem_base + (2*128*GP + buf*128*GP + r*GP + kc*4)*4,
                  &g_Wr[(size_t)(j0 + r)*DIM + k0 + kc*4]);
        }
        cpa_commit();
    };

    issue(0, 0);
    for (int kt = 0; kt < G_NT; kt++) {
        const int buf = kt & 1;
        if (kt + 1 < G_NT) { issue(kt + 1, buf ^ 1); cpa_wait<1>(); }
        else               { cpa_wait<0>(); }
        __syncthreads();

        const unsigned* As = Asm + buf*128*GP;
        const unsigned* Bs = Bsm + buf*128*GP;
        #pragma unroll
        for (int kc = 0; kc < 4; kc++) {
            unsigned a[4][4], b[4][2];
            #pragma unroll
            for (int mt = 0; mt < 4; mt++) {
                a[mt][0] = As[(wm + mt*16 + lr    )*GP + kc*8 + lm    ];
                a[mt][1] = As[(wm + mt*16 + lr + 8)*GP + kc*8 + lm    ];
                a[mt][2] = As[(wm + mt*16 + lr    )*GP + kc*8 + lm + 4];
                a[mt][3] = As[(wm + mt*16 + lr + 8)*GP + kc*8 + lm + 4];
            }
            #pragma unroll
            for (int nt = 0; nt < 4; nt++) {
                b[nt][0] = Bs[(wn + nt*8 + lr)*GP + kc*8 + lm    ];
                b[nt][1] = Bs[(wn + nt*8 + lr)*GP + kc*8 + lm + 4];
            }
            #pragma unroll
            for (int mt = 0; mt < 4; mt++)
                #pragma unroll
                for (int nt = 0; nt < 4; nt++)
                    mma_tf32(acc[mt][nt], a[mt], b[nt]);
        }
        __syncthreads();
    }

    // Epilogue: 128-col tile never crosses the Q/K/V boundary (768 = 6*128)
    // but spans two heads; resolve head per column.
    const int t = j0 / DIM;
    const int jbase = j0 % DIM;
    float* dst = (t == 0) ? g_Q : (t == 1) ? g_K : g_V;
    const bool do_round = (t != 0);

    #pragma unroll
    for (int mt = 0; mt < 4; mt++) {
        #pragma unroll
        for (int half = 0; half < 2; half++) {
            const int gi = i0 + wm + mt*16 + lr + half*8;
            const int pr = indices[gi];
            const int bb = pr / SL;
            const int ss = pr % SL;
            #pragma unroll
            for (int nt = 0; nt < 4; nt++) {
                const int col = wn + nt*8 + 2*lm;
                const int jc = jbase + col;
                const int hh = jc >> 6, dd = jc & 63;
                float2 bv = *(const float2*)&wb[j0 + col];
                float2 o;
                o.x = acc[mt][nt][half*2+0] + bv.x;
                o.y = acc[mt][nt][half*2+1] + bv.y;
                if (do_round) {
                    o.x = __uint_as_float(f2tf(o.x));
                    o.y = __uint_as_float(f2tf(o.y));
                }
                *(float2*)&dst[(((size_t)bb*NH + hh)*SL + ss)*HD + dd] = o;
            }
        }
    }
}

// ---------------------------------------------------------------------------
// Fused attention v6. 256 threads, 128 q-rows/CTA, 8 warps x 16 q-rows, each
// warp covers the full 64-kv tile. __launch_bounds__(256,2) -> 2 CTAs/SM:
// cross-CTA overlap decouples the per-tile barrier (matches the GEMM config
// that runs at the legacy-HMMA floor). Bias loads straight into the S
// accumulators; cp.async double buffer; PV kv-permutation (no shuffles).
// Output goes DIRECTLY to d_out via g_inv (no g_O, no gather kernel).
// ---------------------------------------------------------------------------
#define KPAD 68
#define VPAD 68
#define A_KOFF 0
#define A_VOFF (2*64*KPAD)
#define A_SMEM_WORDS (A_VOFF + 2*64*VPAD)
#define QROWS 128
#define ATHREADS 256
__global__ __launch_bounds__(ATHREADS, 2) void attn_kernel(
    const float* __restrict__ bias, float* __restrict__ out)
{
    extern __shared__ unsigned asm_[];
    const int tid  = threadIdx.x;
    const int lane = tid & 31;
    const int wid  = tid >> 5;           // 0..7
    const int lr = lane >> 2, lm = lane & 3;
    const int bh = blockIdx.y;
    const int b  = bh / NH, h = bh % NH;
    const int q0 = blockIdx.x * QROWS;
    const unsigned smem_base = (unsigned)__cvta_generic_to_shared(asm_);

    const float* qp = g_Q + (size_t)bh * SL * HD;
    const float* kp = g_K + (size_t)bh * SL * HD;
    const float* vp = g_V + (size_t)bh * SL * HD;
    const float* bW = bias + ((size_t)bh * SL + q0 + wid*16) * SL;

    auto issue = [&](int kt, int buf) {
        const int kb = kt * 64;
        #pragma unroll
        for (int t = 0; t < 4; t++) {               // K: 64x64 = 1024 chunks
            int c = tid + t*ATHREADS;
            int kv = c >> 4, dc = c & 15;
            cpa16(smem_base + (A_KOFF + buf*64*KPAD + kv*KPAD + dc*4)*4,
                  &kp[(size_t)(kb + kv)*HD + dc*4]);
        }
        #pragma unroll
        for (int t = 0; t < 4; t++) {               // V: 64x64
            int c = tid + t*ATHREADS;
            int kv = c >> 4, dc = c & 15;
            cpa16(smem_base + (A_VOFF + buf*64*VPAD + kv*VPAD + dc*4)*4,
                  &vp[(size_t)(kb + kv)*HD + dc*4]);
        }
        cpa_commit();
    };

    issue(0, 0);

    // Q fragments (x 1/8) for this warp's 16 rows, loaded once from gmem.
    unsigned qa[8][4];
    {
        const int qrow = q0 + wid*16 + lr;
        #pragma unroll
        for (int kc = 0; kc < 8; kc++) {
            qa[kc][0] = f2tf(0.125f * qp[(size_t)(qrow    )*HD + kc*8 + lm    ]);
            qa[kc][1] = f2tf(0.125f * qp[(size_t)(qrow + 8)*HD + kc*8 + lm    ]);
            qa[kc][2] = f2tf(0.125f * qp[(size_t)(qrow    )*HD + kc*8 + lm + 4]);
            qa[kc][3] = f2tf(0.125f * qp[(size_t)(qrow + 8)*HD + kc*8 + lm + 4]);
        }
    }

    float o[8][4];
    #pragma unroll
    for (int dt = 0; dt < 8; dt++)
        #pragma unroll
        for (int r = 0; r < 4; r++) o[dt][r] = 0.f;
    float l0 = 0.f, l1 = 0.f;

    for (int kt = 0; kt < SL/64; kt++) {
        const int buf = kt & 1;
        if (kt + 1 < SL/64) issue(kt + 1, buf ^ 1);

        // S accumulators initialized with bias straight from gmem (consumed
        // only after the 64-mma QK chain -> DRAM latency hidden).
        float s[8][4];
        {
            const float* bp = bW + kt*64;
            #pragma unroll
            for (int nt = 0; nt < 8; nt++) {
                float2 t0 = *(const float2*)&bp[(size_t)(lr    )*SL + nt*8 + 2*lm];
                float2 t1 = *(const float2*)&bp[(size_t)(lr + 8)*SL + nt*8 + 2*lm];
                s[nt][0] = t0.x; s[nt][1] = t0.y;
                s[nt][2] = t1.x; s[nt][3] = t1.y;
            }
        }

        if (kt + 1 < SL/64) cpa_wait<1>(); else cpa_wait<0>();
        __syncthreads();

        const unsigned* Ks = asm_ + A_KOFF + buf*64*KPAD;
        const unsigned* Vs = asm_ + A_VOFF + buf*64*VPAD;

        // S += (Q/8) K^T over the full 64 kv
        #pragma unroll
        for (int kc = 0; kc < 8; kc++) {
            #pragma unroll
            for (int nt = 0; nt < 8; nt++) {
                unsigned bk[2];
                bk[0] = Ks[(nt*8 + lr)*KPAD + kc*8 + lm    ];
                bk[1] = Ks[(nt*8 + lr)*KPAD + kc*8 + lm + 4];
                mma_tf32(s[nt], qa[kc], bk);
            }
        }

        // P = exp(S); partial row sums
        #pragma unroll
        for (int nt = 0; nt < 8; nt++) {
            s[nt][0] = __expf(s[nt][0]);
            s[nt][1] = __expf(s[nt][1]);
            s[nt][2] = __expf(s[nt][2]);
            s[nt][3] = __expf(s[nt][3]);
            l0 += s[nt][0] + s[nt][1];
            l1 += s[nt][2] + s[nt][3];
        }

        // O += P V with kv permuted pi=[0,2,4,6,1,3,5,7] inside each 8-block:
        // acc layout == A-fragment layout, V B-frag reads rows cb+2lm, cb+2lm+1.
        #pragma unroll
        for (int kc = 0; kc < 8; kc++) {
            const int cb = kc*8;
            unsigned pa[4];
            pa[0] = f2tf(s[kc][0]); pa[1] = f2tf(s[kc][2]);
            pa[2] = f2tf(s[kc][1]); pa[3] = f2tf(s[kc][3]);
            #pragma unroll
            for (int dt = 0; dt < 8; dt++) {
                unsigned bv[2];
                bv[0] = Vs[(cb + 2*lm    )*VPAD + dt*8 + lr];
                bv[1] = Vs[(cb + 2*lm + 1)*VPAD + dt*8 + lr];
                mma_tf32(o[dt], pa, bv);
            }
        }
        __syncthreads();
    }

    // Normalize and store directly to out rows via g_inv (no gather pass).
    l0 += __shfl_xor_sync(0xffffffffu, l0, 1);
    l0 += __shfl_xor_sync(0xffffffffu, l0, 2);
    l1 += __shfl_xor_sync(0xffffffffu, l1, 1);
    l1 += __shfl_xor_sync(0xffffffffu, l1, 2);
    const float inv0 = 1.0f / l0;
    const float inv1 = 1.0f / l1;

    const int prow0 = b*SL + q0 + wid*16 + lr;
    const int or0 = g_inv[prow0];
    const int or1 = g_inv[prow0 + 8];
    if (or0 >= 0) {
        float* orow = &out[(size_t)or0 * DIM + h*HD];
        #pragma unroll
        for (int dt = 0; dt < 8; dt++)
            *(float2*)&orow[dt*8 + 2*lm] = make_float2(o[dt][0]*inv0, o[dt][1]*inv0);
    }
    if (or1 >= 0) {
        float* orow = &out[(size_t)or1 * DIM + h*HD];
        #pragma unroll
        for (int dt = 0; dt < 8; dt++)
            *(float2*)&orow[dt*8 + 2*lm] = make_float2(o[dt][2]*inv1, o[dt][3]*inv1);
    }
}

// ---------------------------------------------------------------------------
extern "C" void kernel_launch(void* const* d_in, const int* in_sizes, int n_in,
                              void* d_out, int out_size)
{
    const float* hidden  = (const float*)d_in[0];
    const int*   indices = (const int*)  d_in[3];
    const float* bias    = (const float*)d_in[5];
    const float* Wqkv_w  = (const float*)d_in[7];
    const float* Wqkv_b  = (const float*)d_in[8];
    const int nnz = in_sizes[0] / DIM;   // 8192

    static bool attr_done = false;
    if (!attr_done) {
        cudaFuncSetAttribute(qkv_gemm_kernel,
            cudaFuncAttributeMaxDynamicSharedMemorySize, G_SMEM_BYTES);
        cudaFuncSetAttribute(attn_kernel,
            cudaFuncAttributeMaxDynamicSharedMemorySize, A_SMEM_WORDS*4);
        attr_done = true;
    }

    prep_kernel<<<2048, 256>>>(hidden, Wqkv_w);
    qkv_gemm_kernel<<<dim3(3*DIM/128, nnz/128), 256, G_SMEM_BYTES>>>(Wqkv_b, indices);
    attn_kernel<<<dim3(SL/QROWS, NB*NH), ATHREADS, A_SMEM_WORDS*4>>>(bias, (float*)d_out);
}